// round 14
// baseline (speedup 1.0000x reference)
#include <cuda_runtime.h>

#define Tn 512
#define Bn 256
#define Hn 32

// Scratch (no cudaMalloc allowed): device globals.
__device__ float g_h0[(size_t)Bn * Tn * 64];          // [B][T][64]  layer-0 output (fwd|bwd)
__device__ float g_gx1[(size_t)2 * Tn * Bn * 128];    // [dir][t][B][128] layer-1 input proj (gate-scaled)
__device__ float g_hn[Bn * 64];                       // [B][64] final hidden (fwd|bwd)
__device__ unsigned g_done;                           // layer1 completion counter (zero-init)

// Activation scaling constants (folded into weights):
//   sig(z)  = rcp(1 + ex2(S*z)),          S = -log2(e)
//   tanh(z) = 1 - 2*rcp(1 + ex2(K*z)),    K = 2*log2(e)
#define SCONST (-1.4426950408889634f)
#define KCONST ( 2.8853900817779268f)

// ---- packed f32x2 helpers ----
__device__ __forceinline__ unsigned long long pack2(float a, float b) {
    unsigned long long r; asm("mov.b64 %0,{%1,%2};" : "=l"(r) : "f"(a), "f"(b)); return r;
}
__device__ __forceinline__ unsigned long long dup2(float a) {
    unsigned long long r; asm("mov.b64 %0,{%1,%1};" : "=l"(r) : "f"(a)); return r;
}
__device__ __forceinline__ void unpack2(unsigned long long v, float& lo, float& hi) {
    asm("mov.b64 {%0,%1},%2;" : "=f"(lo), "=f"(hi) : "l"(v));
}
__device__ __forceinline__ void ffma2(unsigned long long& acc, unsigned long long a,
                                      unsigned long long b) {
    asm("fma.rn.f32x2 %0,%1,%2,%0;" : "+l"(acc) : "l"(a), "l"(b));
}
__device__ __forceinline__ unsigned long long add2(unsigned long long a, unsigned long long b) {
    unsigned long long r; asm("add.rn.f32x2 %0,%1,%2;" : "=l"(r) : "l"(a), "l"(b)); return r;
}

__device__ __forceinline__ float ex2f(float x) {
    float r; asm("ex2.approx.f32 %0,%1;" : "=f"(r) : "f"(x)); return r;
}
__device__ __forceinline__ float rcpf(float x) {
    float r; asm("rcp.approx.f32 %0,%1;" : "=f"(r) : "f"(x)); return r;
}
__device__ __forceinline__ float sig_pre(float zs) {   // zs = S*z
    return rcpf(1.0f + ex2f(zs));
}

// h-exchange through smem without WARPSYNC: STS then LDS from the same
// converged warp are processed in-order by the LSU.
__device__ __forceinline__ void sts_f32(unsigned addr, float v) {
    asm volatile("st.shared.f32 [%0], %1;" :: "r"(addr), "f"(v));
}
__device__ __forceinline__ void lds_v2u64(unsigned addr, unsigned long long& a,
                                          unsigned long long& b) {
    asm volatile("ld.shared.v2.u64 {%0,%1},[%2];" : "=l"(a), "=l"(b) : "r"(addr));
}

__device__ __forceinline__ float combine_z(unsigned long long a0, unsigned long long a1) {
    float lo, hi;
    unpack2(add2(a0, a1), lo, hi);
    return lo + hi;
}

// ---------------------------------------------------------------------------
// Layer-0 bidirectional LSTM (byte-identical hot loop to R13 best).
// ---------------------------------------------------------------------------
__global__ void __launch_bounds__(128, 1) lstm_layer0(
    const float* __restrict__ x,
    const float* __restrict__ wih_f, const float* __restrict__ whh_f,
    const float* __restrict__ bih_f, const float* __restrict__ bhh_f,
    const float* __restrict__ wih_b, const float* __restrict__ whh_b,
    const float* __restrict__ bih_b, const float* __restrict__ bhh_b)
{
    const int dir  = blockIdx.y;
    const int warp = threadIdx.x >> 5;
    const int j    = threadIdx.x & 31;
    const int b    = blockIdx.x * 4 + warp;

    const float* wih = dir ? wih_b : wih_f;
    const float* whh = dir ? whh_b : whh_f;
    const float* bih = dir ? bih_b : bih_f;
    const float* bhh = dir ? bhh_b : bhh_f;

    const float sc[4] = {SCONST, SCONST, KCONST, SCONST};

    unsigned long long wk[4][16];
#pragma unroll
    for (int q = 0; q < 4; q++) {
        const float4* r = reinterpret_cast<const float4*>(whh + (q * 32 + j) * 32);
        const float s = sc[q];
#pragma unroll
        for (int v = 0; v < 8; v++) {
            float4 f = r[v];
            wk[q][2*v]   = pack2(f.x * s, f.y * s);
            wk[q][2*v+1] = pack2(f.z * s, f.w * s);
        }
    }
    float wi[4][3], bias[4];
#pragma unroll
    for (int q = 0; q < 4; q++) {
        const int row = q * 32 + j;
        const float s = sc[q];
        wi[q][0] = wih[row*3+0] * s;
        wi[q][1] = wih[row*3+1] * s;
        wi[q][2] = wih[row*3+2] * s;
        bias[q]  = (bih[row] + bhh[row]) * s;
    }

    __shared__ __align__(16) float hx[4][32];
    const unsigned st_addr = (unsigned)__cvta_generic_to_shared(&hx[warp][j]);
    const unsigned ld_base = (unsigned)__cvta_generic_to_shared(&hx[warp][0]);

    const float* xb = x + (size_t)b * Tn * 3;
    const int xstep = dir ? -3 : 3;
    const float* xpf = dir ? (xb + (Tn - 1) * 3) : xb;
    float pfx[2][3];
#pragma unroll
    for (int s = 0; s < 2; s++) {
        pfx[s][0] = __ldg(xpf + 0);
        pfx[s][1] = __ldg(xpf + 1);
        pfx[s][2] = __ldg(xpf + 2);
        xpf += xstep;
    }

    float* obp = g_h0 + (size_t)b * Tn * 64 + dir * 32 + j
               + (dir ? (size_t)(Tn - 1) * 64 : 0);
    const int ostep = dir ? -64 : 64;

    float h = 0.0f, C = 0.0f;   // C = K * c
    for (int t = 0; t < Tn; t++) {
        const int s = t & 1;

        float zx[4];
#pragma unroll
        for (int q = 0; q < 4; q++)
            zx[q] = fmaf(wi[q][2], pfx[s][2],
                    fmaf(wi[q][1], pfx[s][1],
                    fmaf(wi[q][0], pfx[s][0], bias[q])));

        if (t + 2 < Tn) {
            pfx[s][0] = __ldg(xpf + 0);
            pfx[s][1] = __ldg(xpf + 1);
            pfx[s][2] = __ldg(xpf + 2);
            xpf += xstep;
        }

        sts_f32(st_addr, h);
        unsigned long long hp[16];
#pragma unroll
        for (int v = 0; v < 8; v++) lds_v2u64(ld_base + 16u * v, hp[2*v], hp[2*v+1]);

        // phase 1: gates i,f,g
        unsigned long long a0[3], a1[3];
#pragma unroll
        for (int q = 0; q < 3; q++) { a0[q] = pack2(zx[q], 0.0f); a1[q] = 0ull; }
#pragma unroll
        for (int v = 0; v < 8; v++) {
#pragma unroll
            for (int q = 0; q < 3; q++) {
                ffma2(a0[q], wk[q][2*v],   hp[2*v]);
                ffma2(a1[q], wk[q][2*v+1], hp[2*v+1]);
            }
        }
        const float z0 = combine_z(a0[0], a1[0]);
        const float z1 = combine_z(a0[1], a1[1]);
        const float z2 = combine_z(a0[2], a1[2]);

        const float ig  = sig_pre(z0);
        const float fg  = sig_pre(z1);
        const float ggK = fmaf(-2.0f * KCONST, rcpf(1.0f + ex2f(z2)), KCONST);
        C = fmaf(fg, C, ig * ggK);
        const float eC = ex2f(C);

        // phase 2: o-gate
        unsigned long long b0 = pack2(zx[3], 0.0f), b1 = 0ull;
#pragma unroll
        for (int v = 0; v < 8; v++) {
            ffma2(b0, wk[3][2*v],   hp[2*v]);
            ffma2(b1, wk[3][2*v+1], hp[2*v+1]);
        }
        const float z3 = combine_z(b0, b1);
        const float og = sig_pre(z3);

        const float th = fmaf(-2.0f, rcpf(1.0f + eC), 1.0f);
        h = og * th;

        *obp = h;
        obp += ostep;
    }
}

// ---------------------------------------------------------------------------
// Layer-1 input projection GEMM. CHANGED: 16 timesteps per block (512 blocks
// = single fully-resident wave at 5 blocks/SM; half the weight-tile fills).
// ---------------------------------------------------------------------------
__global__ void __launch_bounds__(128) gx1_gemm(
    const float* __restrict__ wih1_f, const float* __restrict__ bih1_f, const float* __restrict__ bhh1_f,
    const float* __restrict__ wih1_b, const float* __restrict__ bih1_b, const float* __restrict__ bhh1_b)
{
    const int t0  = blockIdx.x * 16;
    const int b0  = blockIdx.y * 32;
    const int dir = blockIdx.z;
    const float* w  = dir ? wih1_b : wih1_f;
    const float* bi = dir ? bih1_b : bih1_f;
    const float* bh = dir ? bhh1_b : bhh1_f;

    __shared__ __align__(16) float w_s[64 * 132];
    __shared__ __align__(16) float h_s[64 * 36];
    __shared__ float bias_s[128];

    const int tid = threadIdx.x;
    for (int i = tid; i < 128 * 64; i += 128) {
        const int k = i & 63, g = i >> 6;
        const float s = ((g >> 5) == 2) ? KCONST : SCONST;
        w_s[k * 132 + g] = w[g * 64 + k] * s;
    }
    {
        const float s = ((tid >> 5) == 2) ? KCONST : SCONST;
        bias_s[tid] = (bi[tid] + bh[tid]) * s;
    }

    const int gl = (tid & 31) * 4;
    const int bq = tid >> 5;
    const unsigned h_base = (unsigned)__cvta_generic_to_shared(&h_s[0]) + bq * 32u;

    for (int it = 0; it < 16; it++) {
        const int t = t0 + it;
        __syncthreads();
        for (int i = tid; i < 32 * 64; i += 128) {
            const int k = i & 63, bb = i >> 6;
            h_s[k * 36 + bb] = g_h0[((size_t)(b0 + bb) * Tn + t) * 64 + k];
        }
        __syncthreads();

        unsigned long long acc[4][4];
#pragma unroll
        for (int g = 0; g < 4; g++) {
            unsigned long long bg = dup2(bias_s[gl + g]);
#pragma unroll
            for (int p = 0; p < 4; p++) acc[g][p] = bg;
        }

#pragma unroll 4
        for (int k = 0; k < 64; k++) {
            const float4 wv = *reinterpret_cast<const float4*>(&w_s[k * 132 + gl]);
            unsigned long long wd[4];
            wd[0] = dup2(wv.x); wd[1] = dup2(wv.y); wd[2] = dup2(wv.z); wd[3] = dup2(wv.w);
            unsigned long long hp[4];
            lds_v2u64(h_base + (unsigned)(k * 144),      hp[0], hp[1]);
            lds_v2u64(h_base + (unsigned)(k * 144) + 16, hp[2], hp[3]);
#pragma unroll
            for (int g = 0; g < 4; g++)
#pragma unroll
                for (int p = 0; p < 4; p++) ffma2(acc[g][p], wd[g], hp[p]);
        }

        float* outb = g_gx1 + (((size_t)dir * Tn + t) * Bn + b0 + bq * 8) * 128 + gl;
#pragma unroll
        for (int p = 0; p < 4; p++) {
            float v0e, v0o, v1e, v1o, v2e, v2o, v3e, v3o;
            unpack2(acc[0][p], v0e, v0o);
            unpack2(acc[1][p], v1e, v1o);
            unpack2(acc[2][p], v2e, v2o);
            unpack2(acc[3][p], v3e, v3o);
            float4 lo = make_float4(v0e, v1e, v2e, v3e);
            float4 hi = make_float4(v0o, v1o, v2o, v3o);
            *reinterpret_cast<float4*>(outb + (size_t)(2 * p) * 128)     = lo;
            *reinterpret_cast<float4*>(outb + (size_t)(2 * p + 1) * 128) = hi;
        }
    }
}

// ---------------------------------------------------------------------------
// Layer-1 bidirectional LSTM + fused classifier tail (threadfence-reduction:
// the 128th block to finish runs the 256-row classifier and resets g_done).
// Hot loop byte-identical to R13.
// ---------------------------------------------------------------------------
__global__ void __launch_bounds__(128, 1) lstm_layer1(
    const float* __restrict__ whh_f, const float* __restrict__ whh_b,
    const float* __restrict__ wc1, const float* __restrict__ bc1,
    const float* __restrict__ wc2, const float* __restrict__ bc2,
    float* __restrict__ out)
{
    const int dir  = blockIdx.y;
    const int warp = threadIdx.x >> 5;
    const int j    = threadIdx.x & 31;
    const int b    = blockIdx.x * 4 + warp;
    const float* whh = dir ? whh_b : whh_f;

    const float sc[4] = {SCONST, SCONST, KCONST, SCONST};
    unsigned long long wk[4][16];
#pragma unroll
    for (int q = 0; q < 4; q++) {
        const float4* r = reinterpret_cast<const float4*>(whh + (q * 32 + j) * 32);
        const float s = sc[q];
#pragma unroll
        for (int v = 0; v < 8; v++) {
            float4 f = r[v];
            wk[q][2*v]   = pack2(f.x * s, f.y * s);
            wk[q][2*v+1] = pack2(f.z * s, f.w * s);
        }
    }

    __shared__ __align__(16) float hx[4][32];
    const unsigned st_addr = (unsigned)__cvta_generic_to_shared(&hx[warp][j]);
    const unsigned ld_base = (unsigned)__cvta_generic_to_shared(&hx[warp][0]);

    const long long gstep = dir ? -(long long)Bn * 128 : (long long)Bn * 128;
    const float* gpf = g_gx1 + (size_t)dir * Tn * Bn * 128 + (size_t)b * 128 + j
                     + (dir ? (size_t)(Tn - 1) * Bn * 128 : 0);

    float pf[4][4];
#pragma unroll
    for (int s = 0; s < 4; s++) {
#pragma unroll
        for (int q = 0; q < 4; q++) pf[s][q] = __ldg(gpf + q * 32);
        gpf += gstep;
    }

    float h = 0.0f, C = 0.0f;
    for (int t = 0; t < Tn; t++) {
        const int s = t & 3;
        float zx[4];
#pragma unroll
        for (int q = 0; q < 4; q++) zx[q] = pf[s][q];

        if (t + 4 < Tn) {
#pragma unroll
            for (int q = 0; q < 4; q++) pf[s][q] = __ldg(gpf + q * 32);
            gpf += gstep;
        }

        sts_f32(st_addr, h);
        unsigned long long hp[16];
#pragma unroll
        for (int v = 0; v < 8; v++) lds_v2u64(ld_base + 16u * v, hp[2*v], hp[2*v+1]);

        // phase 1: i,f,g
        unsigned long long a0[3], a1[3];
#pragma unroll
        for (int q = 0; q < 3; q++) { a0[q] = pack2(zx[q], 0.0f); a1[q] = 0ull; }
#pragma unroll
        for (int v = 0; v < 8; v++) {
#pragma unroll
            for (int q = 0; q < 3; q++) {
                ffma2(a0[q], wk[q][2*v],   hp[2*v]);
                ffma2(a1[q], wk[q][2*v+1], hp[2*v+1]);
            }
        }
        const float z0 = combine_z(a0[0], a1[0]);
        const float z1 = combine_z(a0[1], a1[1]);
        const float z2 = combine_z(a0[2], a1[2]);

        const float ig  = sig_pre(z0);
        const float fg  = sig_pre(z1);
        const float ggK = fmaf(-2.0f * KCONST, rcpf(1.0f + ex2f(z2)), KCONST);
        C = fmaf(fg, C, ig * ggK);
        const float eC = ex2f(C);

        // phase 2: o-gate
        unsigned long long b0 = pack2(zx[3], 0.0f), b1 = 0ull;
#pragma unroll
        for (int v = 0; v < 8; v++) {
            ffma2(b0, wk[3][2*v],   hp[2*v]);
            ffma2(b1, wk[3][2*v+1], hp[2*v+1]);
        }
        const float z3 = combine_z(b0, b1);
        const float og = sig_pre(z3);

        const float th = fmaf(-2.0f, rcpf(1.0f + eC), 1.0f);
        h = og * th;
    }

    g_hn[b * 64 + dir * 32 + j] = h;

    // ---- fused classifier tail (last block of 128) ----
    __shared__ unsigned is_last;
    __threadfence();
    __syncthreads();
    if (threadIdx.x == 0) {
        unsigned old = atomicAdd(&g_done, 1u);
        is_last = (old == 127u) ? 1u : 0u;
    }
    __syncthreads();
    if (is_last) {
        if (threadIdx.x == 0) g_done = 0;   // reset for next graph replay
        // 4 warps x 64 rows; lane j = hidden neuron j.
        const float4* wr = reinterpret_cast<const float4*>(wc1 + j * 64);
        const float bc1j = __ldg(bc1 + j);
        const float w2a  = __ldg(wc2 + j);
        const float w2b  = __ldg(wc2 + 32 + j);
        const float b2a  = __ldg(bc2 + 0);
        const float b2b  = __ldg(bc2 + 1);
        for (int r = 0; r < 64; r++) {
            const int row = warp * 64 + r;
            const float4* hr = reinterpret_cast<const float4*>(g_hn + row * 64);
            float a = bc1j;
#pragma unroll
            for (int v = 0; v < 16; v++) {
                float4 w4 = __ldg(wr + v);
                float4 h4 = __ldg(hr + v);
                a += w4.x * h4.x + w4.y * h4.y + w4.z * h4.z + w4.w * h4.w;
            }
            a = fmaxf(a, 0.0f);
            float p0 = a * w2a;
            float p1 = a * w2b;
#pragma unroll
            for (int off = 16; off > 0; off >>= 1) {
                p0 += __shfl_xor_sync(0xffffffffu, p0, off);
                p1 += __shfl_xor_sync(0xffffffffu, p1, off);
            }
            if (j == 0) {
                out[row * 2 + 0] = p0 + b2a;
                out[row * 2 + 1] = p1 + b2b;
            }
        }
    }
}

// ---------------------------------------------------------------------------
extern "C" void kernel_launch(void* const* d_in, const int* in_sizes, int n_in,
                              void* d_out, int out_size)
{
    (void)in_sizes; (void)n_in; (void)out_size;
    const float* x     = (const float*)d_in[0];
    const float* wih0f = (const float*)d_in[1];
    const float* whh0f = (const float*)d_in[2];
    const float* bih0f = (const float*)d_in[3];
    const float* bhh0f = (const float*)d_in[4];
    const float* wih0b = (const float*)d_in[5];
    const float* whh0b = (const float*)d_in[6];
    const float* bih0b = (const float*)d_in[7];
    const float* bhh0b = (const float*)d_in[8];
    const float* wih1f = (const float*)d_in[9];
    const float* whh1f = (const float*)d_in[10];
    const float* bih1f = (const float*)d_in[11];
    const float* bhh1f = (const float*)d_in[12];
    const float* wih1b = (const float*)d_in[13];
    const float* whh1b = (const float*)d_in[14];
    const float* bih1b = (const float*)d_in[15];
    const float* bhh1b = (const float*)d_in[16];
    const float* wc1   = (const float*)d_in[17];
    const float* bc1   = (const float*)d_in[18];
    const float* wc2   = (const float*)d_in[19];
    const float* bc2   = (const float*)d_in[20];

    lstm_layer0<<<dim3(Bn / 4, 2), 128>>>(x, wih0f, whh0f, bih0f, bhh0f,
                                          wih0b, whh0b, bih0b, bhh0b);
    gx1_gemm<<<dim3(Tn / 16, Bn / 32, 2), 128>>>(wih1f, bih1f, bhh1f,
                                                 wih1b, bih1b, bhh1b);
    lstm_layer1<<<dim3(Bn / 4, 2), 128>>>(whh1f, whh1b,
                                          wc1, bc1, wc2, bc2, (float*)d_out);
}

// round 15
// speedup vs baseline: 1.0465x; 1.0465x over previous
#include <cuda_runtime.h>

#define Tn 512
#define Bn 256
#define Hn 32

// Scratch (no cudaMalloc allowed): device globals.
__device__ float g_h0[(size_t)Bn * Tn * 64];          // [B][T][64]  layer-0 output (fwd|bwd)
__device__ float g_gx1[(size_t)2 * Tn * Bn * 128];    // [dir][t][B][128] layer-1 input proj (gate-scaled)
__device__ float g_hn[Bn * 64];                       // [B][64] final hidden (fwd|bwd)

// Activation scaling constants (folded into weights):
//   sig(z)  = rcp(1 + ex2(S*z)),          S = -log2(e)
//   tanh(z) = 1 - 2*rcp(1 + ex2(K*z)),    K = 2*log2(e)
#define SCONST (-1.4426950408889634f)
#define KCONST ( 2.8853900817779268f)

// ---- packed f32x2 helpers ----
__device__ __forceinline__ unsigned long long pack2(float a, float b) {
    unsigned long long r; asm("mov.b64 %0,{%1,%2};" : "=l"(r) : "f"(a), "f"(b)); return r;
}
__device__ __forceinline__ unsigned long long dup2(float a) {
    unsigned long long r; asm("mov.b64 %0,{%1,%1};" : "=l"(r) : "f"(a)); return r;
}
__device__ __forceinline__ void unpack2(unsigned long long v, float& lo, float& hi) {
    asm("mov.b64 {%0,%1},%2;" : "=f"(lo), "=f"(hi) : "l"(v));
}
__device__ __forceinline__ void ffma2(unsigned long long& acc, unsigned long long a,
                                      unsigned long long b) {
    asm("fma.rn.f32x2 %0,%1,%2,%0;" : "+l"(acc) : "l"(a), "l"(b));
}
__device__ __forceinline__ unsigned long long add2(unsigned long long a, unsigned long long b) {
    unsigned long long r; asm("add.rn.f32x2 %0,%1,%2;" : "=l"(r) : "l"(a), "l"(b)); return r;
}

__device__ __forceinline__ float ex2f(float x) {
    float r; asm("ex2.approx.f32 %0,%1;" : "=f"(r) : "f"(x)); return r;
}
__device__ __forceinline__ float rcpf(float x) {
    float r; asm("rcp.approx.f32 %0,%1;" : "=f"(r) : "f"(x)); return r;
}
__device__ __forceinline__ float sig_pre(float zs) {   // zs = S*z
    return rcpf(1.0f + ex2f(zs));
}

// h-exchange through smem without WARPSYNC: STS then LDS from the same
// converged warp are processed in-order by the LSU.
__device__ __forceinline__ void sts_f32(unsigned addr, float v) {
    asm volatile("st.shared.f32 [%0], %1;" :: "r"(addr), "f"(v));
}
__device__ __forceinline__ void lds_v2u64(unsigned addr, unsigned long long& a,
                                          unsigned long long& b) {
    asm volatile("ld.shared.v2.u64 {%0,%1},[%2];" : "=l"(a), "=l"(b) : "r"(addr));
}

__device__ __forceinline__ float combine_z(unsigned long long a0, unsigned long long a1) {
    float lo, hi;
    unpack2(add2(a0, a1), lo, hi);
    return lo + hi;
}

// ---------------------------------------------------------------------------
// Layer-0 bidirectional LSTM (byte-identical to R13 best / 392us).
// ---------------------------------------------------------------------------
__global__ void __launch_bounds__(128, 1) lstm_layer0(
    const float* __restrict__ x,
    const float* __restrict__ wih_f, const float* __restrict__ whh_f,
    const float* __restrict__ bih_f, const float* __restrict__ bhh_f,
    const float* __restrict__ wih_b, const float* __restrict__ whh_b,
    const float* __restrict__ bih_b, const float* __restrict__ bhh_b)
{
    const int dir  = blockIdx.y;
    const int warp = threadIdx.x >> 5;
    const int j    = threadIdx.x & 31;
    const int b    = blockIdx.x * 4 + warp;

    const float* wih = dir ? wih_b : wih_f;
    const float* whh = dir ? whh_b : whh_f;
    const float* bih = dir ? bih_b : bih_f;
    const float* bhh = dir ? bhh_b : bhh_f;

    const float sc[4] = {SCONST, SCONST, KCONST, SCONST};

    unsigned long long wk[4][16];
#pragma unroll
    for (int q = 0; q < 4; q++) {
        const float4* r = reinterpret_cast<const float4*>(whh + (q * 32 + j) * 32);
        const float s = sc[q];
#pragma unroll
        for (int v = 0; v < 8; v++) {
            float4 f = r[v];
            wk[q][2*v]   = pack2(f.x * s, f.y * s);
            wk[q][2*v+1] = pack2(f.z * s, f.w * s);
        }
    }
    float wi[4][3], bias[4];
#pragma unroll
    for (int q = 0; q < 4; q++) {
        const int row = q * 32 + j;
        const float s = sc[q];
        wi[q][0] = wih[row*3+0] * s;
        wi[q][1] = wih[row*3+1] * s;
        wi[q][2] = wih[row*3+2] * s;
        bias[q]  = (bih[row] + bhh[row]) * s;
    }

    __shared__ __align__(16) float hx[4][32];
    const unsigned st_addr = (unsigned)__cvta_generic_to_shared(&hx[warp][j]);
    const unsigned ld_base = (unsigned)__cvta_generic_to_shared(&hx[warp][0]);

    const float* xb = x + (size_t)b * Tn * 3;
    const int xstep = dir ? -3 : 3;
    const float* xpf = dir ? (xb + (Tn - 1) * 3) : xb;
    float pfx[2][3];
#pragma unroll
    for (int s = 0; s < 2; s++) {
        pfx[s][0] = __ldg(xpf + 0);
        pfx[s][1] = __ldg(xpf + 1);
        pfx[s][2] = __ldg(xpf + 2);
        xpf += xstep;
    }

    float* obp = g_h0 + (size_t)b * Tn * 64 + dir * 32 + j
               + (dir ? (size_t)(Tn - 1) * 64 : 0);
    const int ostep = dir ? -64 : 64;

    float h = 0.0f, C = 0.0f;   // C = K * c
    for (int t = 0; t < Tn; t++) {
        const int s = t & 1;

        float zx[4];
#pragma unroll
        for (int q = 0; q < 4; q++)
            zx[q] = fmaf(wi[q][2], pfx[s][2],
                    fmaf(wi[q][1], pfx[s][1],
                    fmaf(wi[q][0], pfx[s][0], bias[q])));

        if (t + 2 < Tn) {
            pfx[s][0] = __ldg(xpf + 0);
            pfx[s][1] = __ldg(xpf + 1);
            pfx[s][2] = __ldg(xpf + 2);
            xpf += xstep;
        }

        sts_f32(st_addr, h);
        unsigned long long hp[16];
#pragma unroll
        for (int v = 0; v < 8; v++) lds_v2u64(ld_base + 16u * v, hp[2*v], hp[2*v+1]);

        // phase 1: gates i,f,g
        unsigned long long a0[3], a1[3];
#pragma unroll
        for (int q = 0; q < 3; q++) { a0[q] = pack2(zx[q], 0.0f); a1[q] = 0ull; }
#pragma unroll
        for (int v = 0; v < 8; v++) {
#pragma unroll
            for (int q = 0; q < 3; q++) {
                ffma2(a0[q], wk[q][2*v],   hp[2*v]);
                ffma2(a1[q], wk[q][2*v+1], hp[2*v+1]);
            }
        }
        const float z0 = combine_z(a0[0], a1[0]);
        const float z1 = combine_z(a0[1], a1[1]);
        const float z2 = combine_z(a0[2], a1[2]);

        const float ig  = sig_pre(z0);
        const float fg  = sig_pre(z1);
        const float ggK = fmaf(-2.0f * KCONST, rcpf(1.0f + ex2f(z2)), KCONST);
        C = fmaf(fg, C, ig * ggK);
        const float eC = ex2f(C);

        // phase 2: o-gate
        unsigned long long b0 = pack2(zx[3], 0.0f), b1 = 0ull;
#pragma unroll
        for (int v = 0; v < 8; v++) {
            ffma2(b0, wk[3][2*v],   hp[2*v]);
            ffma2(b1, wk[3][2*v+1], hp[2*v+1]);
        }
        const float z3 = combine_z(b0, b1);
        const float og = sig_pre(z3);

        const float th = fmaf(-2.0f, rcpf(1.0f + eC), 1.0f);
        h = og * th;

        *obp = h;
        obp += ostep;
    }
}

// ---------------------------------------------------------------------------
// Layer-1 input projection GEMM — retiled: 64-thread blocks, thread tile
// 8 gates x 8 batch (aux 12 instrs per 32 FFMA2), block tile 128g x 32b x 16t,
// 512 blocks = single resident wave. k-serial sum order — numerics identical.
// ---------------------------------------------------------------------------
__global__ void __launch_bounds__(64) gx1_gemm(
    const float* __restrict__ wih1_f, const float* __restrict__ bih1_f, const float* __restrict__ bhh1_f,
    const float* __restrict__ wih1_b, const float* __restrict__ bih1_b, const float* __restrict__ bhh1_b)
{
    const int t0  = blockIdx.x * 16;
    const int b0  = blockIdx.y * 32;
    const int dir = blockIdx.z;
    const float* w  = dir ? wih1_b : wih1_f;
    const float* bi = dir ? bih1_b : bih1_f;
    const float* bh = dir ? bhh1_b : bhh1_f;

    __shared__ __align__(16) float w_s[64 * 132];   // [k][g]
    __shared__ __align__(16) float h_s[64 * 36];    // [k][b]
    __shared__ float bias_s[128];

    const int tid = threadIdx.x;
    for (int i = tid; i < 128 * 64; i += 64) {
        const int k = i & 63, g = i >> 6;
        const float s = ((g >> 5) == 2) ? KCONST : SCONST;
        w_s[k * 132 + g] = w[g * 64 + k] * s;
    }
    for (int i = tid; i < 128; i += 64) {
        const float s = ((i >> 5) == 2) ? KCONST : SCONST;
        bias_s[i] = (bi[i] + bh[i]) * s;
    }

    const int ga = (tid & 15) * 4;    // gates ga..ga+3
    const int gb = 64 + ga;           // gates gb..gb+3
    const int bq = tid >> 4;          // batch octet 0..3
    const unsigned h_base = (unsigned)__cvta_generic_to_shared(&h_s[0]) + bq * 32u;

    for (int it = 0; it < 16; it++) {
        const int t = t0 + it;
        __syncthreads();
        // h fill: lanes map to consecutive batch rows -> conflict-free STS.
        for (int i = tid; i < 512; i += 64) {      // 512 float4 groups
            const int bb = i & 31, kq = (i >> 5) & 15;
            const float4 v = *reinterpret_cast<const float4*>(
                &g_h0[((size_t)(b0 + bb) * Tn + t) * 64 + kq * 4]);
            h_s[(kq * 4 + 0) * 36 + bb] = v.x;
            h_s[(kq * 4 + 1) * 36 + bb] = v.y;
            h_s[(kq * 4 + 2) * 36 + bb] = v.z;
            h_s[(kq * 4 + 3) * 36 + bb] = v.w;
        }
        __syncthreads();

        unsigned long long acc[8][4];
#pragma unroll
        for (int g = 0; g < 4; g++) {
            const unsigned long long bgA = dup2(bias_s[ga + g]);
            const unsigned long long bgB = dup2(bias_s[gb + g]);
#pragma unroll
            for (int p = 0; p < 4; p++) { acc[g][p] = bgA; acc[4 + g][p] = bgB; }
        }

#pragma unroll 4
        for (int k = 0; k < 64; k++) {
            const float4 wA = *reinterpret_cast<const float4*>(&w_s[k * 132 + ga]);
            const float4 wB = *reinterpret_cast<const float4*>(&w_s[k * 132 + gb]);
            unsigned long long wd[8];
            wd[0] = dup2(wA.x); wd[1] = dup2(wA.y); wd[2] = dup2(wA.z); wd[3] = dup2(wA.w);
            wd[4] = dup2(wB.x); wd[5] = dup2(wB.y); wd[6] = dup2(wB.z); wd[7] = dup2(wB.w);
            unsigned long long hp[4];
            lds_v2u64(h_base + (unsigned)(k * 144),      hp[0], hp[1]);
            lds_v2u64(h_base + (unsigned)(k * 144) + 16, hp[2], hp[3]);
#pragma unroll
            for (int g = 0; g < 8; g++)
#pragma unroll
                for (int p = 0; p < 4; p++) ffma2(acc[g][p], wd[g], hp[p]);
        }

        float* outb = g_gx1 + (((size_t)dir * Tn + t) * Bn + b0 + bq * 8) * 128;
#pragma unroll
        for (int p = 0; p < 4; p++) {
            float eA0, oA0, eA1, oA1, eA2, oA2, eA3, oA3;
            float eB0, oB0, eB1, oB1, eB2, oB2, eB3, oB3;
            unpack2(acc[0][p], eA0, oA0); unpack2(acc[1][p], eA1, oA1);
            unpack2(acc[2][p], eA2, oA2); unpack2(acc[3][p], eA3, oA3);
            unpack2(acc[4][p], eB0, oB0); unpack2(acc[5][p], eB1, oB1);
            unpack2(acc[6][p], eB2, oB2); unpack2(acc[7][p], eB3, oB3);
            float* rowE = outb + (size_t)(2 * p) * 128;
            float* rowO = rowE + 128;
            *reinterpret_cast<float4*>(rowE + ga) = make_float4(eA0, eA1, eA2, eA3);
            *reinterpret_cast<float4*>(rowE + gb) = make_float4(eB0, eB1, eB2, eB3);
            *reinterpret_cast<float4*>(rowO + ga) = make_float4(oA0, oA1, oA2, oA3);
            *reinterpret_cast<float4*>(rowO + gb) = make_float4(oB0, oB1, oB2, oB3);
        }
    }
}

// ---------------------------------------------------------------------------
// Layer-1 bidirectional LSTM (byte-identical to R13 best).
// ---------------------------------------------------------------------------
__global__ void __launch_bounds__(128, 1) lstm_layer1(
    const float* __restrict__ whh_f, const float* __restrict__ whh_b)
{
    const int dir  = blockIdx.y;
    const int warp = threadIdx.x >> 5;
    const int j    = threadIdx.x & 31;
    const int b    = blockIdx.x * 4 + warp;
    const float* whh = dir ? whh_b : whh_f;

    const float sc[4] = {SCONST, SCONST, KCONST, SCONST};
    unsigned long long wk[4][16];
#pragma unroll
    for (int q = 0; q < 4; q++) {
        const float4* r = reinterpret_cast<const float4*>(whh + (q * 32 + j) * 32);
        const float s = sc[q];
#pragma unroll
        for (int v = 0; v < 8; v++) {
            float4 f = r[v];
            wk[q][2*v]   = pack2(f.x * s, f.y * s);
            wk[q][2*v+1] = pack2(f.z * s, f.w * s);
        }
    }

    __shared__ __align__(16) float hx[4][32];
    const unsigned st_addr = (unsigned)__cvta_generic_to_shared(&hx[warp][j]);
    const unsigned ld_base = (unsigned)__cvta_generic_to_shared(&hx[warp][0]);

    const long long gstep = dir ? -(long long)Bn * 128 : (long long)Bn * 128;
    const float* gpf = g_gx1 + (size_t)dir * Tn * Bn * 128 + (size_t)b * 128 + j
                     + (dir ? (size_t)(Tn - 1) * Bn * 128 : 0);

    float pf[4][4];
#pragma unroll
    for (int s = 0; s < 4; s++) {
#pragma unroll
        for (int q = 0; q < 4; q++) pf[s][q] = __ldg(gpf + q * 32);
        gpf += gstep;
    }

    float h = 0.0f, C = 0.0f;
    for (int t = 0; t < Tn; t++) {
        const int s = t & 3;
        float zx[4];
#pragma unroll
        for (int q = 0; q < 4; q++) zx[q] = pf[s][q];

        if (t + 4 < Tn) {
#pragma unroll
            for (int q = 0; q < 4; q++) pf[s][q] = __ldg(gpf + q * 32);
            gpf += gstep;
        }

        sts_f32(st_addr, h);
        unsigned long long hp[16];
#pragma unroll
        for (int v = 0; v < 8; v++) lds_v2u64(ld_base + 16u * v, hp[2*v], hp[2*v+1]);

        // phase 1: i,f,g
        unsigned long long a0[3], a1[3];
#pragma unroll
        for (int q = 0; q < 3; q++) { a0[q] = pack2(zx[q], 0.0f); a1[q] = 0ull; }
#pragma unroll
        for (int v = 0; v < 8; v++) {
#pragma unroll
            for (int q = 0; q < 3; q++) {
                ffma2(a0[q], wk[q][2*v],   hp[2*v]);
                ffma2(a1[q], wk[q][2*v+1], hp[2*v+1]);
            }
        }
        const float z0 = combine_z(a0[0], a1[0]);
        const float z1 = combine_z(a0[1], a1[1]);
        const float z2 = combine_z(a0[2], a1[2]);

        const float ig  = sig_pre(z0);
        const float fg  = sig_pre(z1);
        const float ggK = fmaf(-2.0f * KCONST, rcpf(1.0f + ex2f(z2)), KCONST);
        C = fmaf(fg, C, ig * ggK);
        const float eC = ex2f(C);

        // phase 2: o-gate
        unsigned long long b0 = pack2(zx[3], 0.0f), b1 = 0ull;
#pragma unroll
        for (int v = 0; v < 8; v++) {
            ffma2(b0, wk[3][2*v],   hp[2*v]);
            ffma2(b1, wk[3][2*v+1], hp[2*v+1]);
        }
        const float z3 = combine_z(b0, b1);
        const float og = sig_pre(z3);

        const float th = fmaf(-2.0f, rcpf(1.0f + eC), 1.0f);
        h = og * th;
    }

    g_hn[b * 64 + dir * 32 + j] = h;
}

// ---------------------------------------------------------------------------
// Classifier (byte-identical to R13 best).
// ---------------------------------------------------------------------------
__global__ void __launch_bounds__(256) classifier(
    const float* __restrict__ wc1, const float* __restrict__ bc1,
    const float* __restrict__ wc2, const float* __restrict__ bc2,
    float* __restrict__ out)
{
    const int warp = threadIdx.x >> 5;
    const int j    = threadIdx.x & 31;
    const int row  = blockIdx.x * 8 + warp;

    const float4* wr = reinterpret_cast<const float4*>(wc1 + j * 64);
    const float4* hr = reinterpret_cast<const float4*>(g_hn + row * 64);

    float a = __ldg(bc1 + j);
#pragma unroll
    for (int v = 0; v < 16; v++) {
        float4 w4 = __ldg(wr + v);
        float4 h4 = __ldg(hr + v);
        a += w4.x * h4.x + w4.y * h4.y + w4.z * h4.z + w4.w * h4.w;
    }
    a = fmaxf(a, 0.0f);
    float p0 = a * __ldg(wc2 + j);
    float p1 = a * __ldg(wc2 + 32 + j);
#pragma unroll
    for (int off = 16; off > 0; off >>= 1) {
        p0 += __shfl_xor_sync(0xffffffffu, p0, off);
        p1 += __shfl_xor_sync(0xffffffffu, p1, off);
    }
    if (j == 0) {
        out[row * 2 + 0] = p0 + __ldg(bc2 + 0);
        out[row * 2 + 1] = p1 + __ldg(bc2 + 1);
    }
}

// ---------------------------------------------------------------------------
extern "C" void kernel_launch(void* const* d_in, const int* in_sizes, int n_in,
                              void* d_out, int out_size)
{
    (void)in_sizes; (void)n_in; (void)out_size;
    const float* x     = (const float*)d_in[0];
    const float* wih0f = (const float*)d_in[1];
    const float* whh0f = (const float*)d_in[2];
    const float* bih0f = (const float*)d_in[3];
    const float* bhh0f = (const float*)d_in[4];
    const float* wih0b = (const float*)d_in[5];
    const float* whh0b = (const float*)d_in[6];
    const float* bih0b = (const float*)d_in[7];
    const float* bhh0b = (const float*)d_in[8];
    const float* wih1f = (const float*)d_in[9];
    const float* whh1f = (const float*)d_in[10];
    const float* bih1f = (const float*)d_in[11];
    const float* bhh1f = (const float*)d_in[12];
    const float* wih1b = (const float*)d_in[13];
    const float* whh1b = (const float*)d_in[14];
    const float* bih1b = (const float*)d_in[15];
    const float* bhh1b = (const float*)d_in[16];
    const float* wc1   = (const float*)d_in[17];
    const float* bc1   = (const float*)d_in[18];
    const float* wc2   = (const float*)d_in[19];
    const float* bc2   = (const float*)d_in[20];

    lstm_layer0<<<dim3(Bn / 4, 2), 128>>>(x, wih0f, whh0f, bih0f, bhh0f,
                                          wih0b, whh0b, bih0b, bhh0b);
    gx1_gemm<<<dim3(Tn / 16, Bn / 32, 2), 64>>>(wih1f, bih1f, bhh1f,
                                                wih1b, bih1b, bhh1b);
    lstm_layer1<<<dim3(Bn / 4, 2), 128>>>(whh1f, whh1b);
    classifier<<<dim3(Bn / 8), 256>>>(wc1, bc1, wc2, bc2, (float*)d_out);
}

// round 16
// speedup vs baseline: 1.1085x; 1.0593x over previous
#include <cuda_runtime.h>

#define Tn 512
#define Bn 256
#define Hn 32

// Scratch (no cudaMalloc allowed): device globals.
__device__ float g_h0[(size_t)Bn * Tn * 64];          // [B][T][64]  layer-0 output (fwd|bwd)
__device__ float g_gx1[(size_t)2 * Tn * Bn * 128];    // [dir][t][B][128] layer-1 input proj (gate-scaled)
__device__ float g_hn[Bn * 64];                       // [B][64] final hidden (fwd|bwd)
__device__ unsigned g_pair_done[Bn / 4];              // per block-pair completion counters (zero-init)

// Activation scaling constants (folded into weights):
//   sig(z)  = rcp(1 + ex2(S*z)),          S = -log2(e)
//   tanh(z) = 1 - 2*rcp(1 + ex2(K*z)),    K = 2*log2(e)
#define SCONST (-1.4426950408889634f)
#define KCONST ( 2.8853900817779268f)

// ---- packed f32x2 helpers ----
__device__ __forceinline__ unsigned long long pack2(float a, float b) {
    unsigned long long r; asm("mov.b64 %0,{%1,%2};" : "=l"(r) : "f"(a), "f"(b)); return r;
}
__device__ __forceinline__ unsigned long long dup2(float a) {
    unsigned long long r; asm("mov.b64 %0,{%1,%1};" : "=l"(r) : "f"(a)); return r;
}
__device__ __forceinline__ void unpack2(unsigned long long v, float& lo, float& hi) {
    asm("mov.b64 {%0,%1},%2;" : "=f"(lo), "=f"(hi) : "l"(v));
}
__device__ __forceinline__ void ffma2(unsigned long long& acc, unsigned long long a,
                                      unsigned long long b) {
    asm("fma.rn.f32x2 %0,%1,%2,%0;" : "+l"(acc) : "l"(a), "l"(b));
}
__device__ __forceinline__ unsigned long long add2(unsigned long long a, unsigned long long b) {
    unsigned long long r; asm("add.rn.f32x2 %0,%1,%2;" : "=l"(r) : "l"(a), "l"(b)); return r;
}

__device__ __forceinline__ float ex2f(float x) {
    float r; asm("ex2.approx.f32 %0,%1;" : "=f"(r) : "f"(x)); return r;
}
__device__ __forceinline__ float rcpf(float x) {
    float r; asm("rcp.approx.f32 %0,%1;" : "=f"(r) : "f"(x)); return r;
}
__device__ __forceinline__ float sig_pre(float zs) {   // zs = S*z
    return rcpf(1.0f + ex2f(zs));
}

// h-exchange through smem without WARPSYNC: STS then LDS from the same
// converged warp are processed in-order by the LSU.
__device__ __forceinline__ void sts_f32(unsigned addr, float v) {
    asm volatile("st.shared.f32 [%0], %1;" :: "r"(addr), "f"(v));
}
__device__ __forceinline__ void lds_v2u64(unsigned addr, unsigned long long& a,
                                          unsigned long long& b) {
    asm volatile("ld.shared.v2.u64 {%0,%1},[%2];" : "=l"(a), "=l"(b) : "r"(addr));
}

__device__ __forceinline__ float combine_z(unsigned long long a0, unsigned long long a1) {
    float lo, hi;
    unpack2(add2(a0, a1), lo, hi);
    return lo + hi;
}

// ---------------------------------------------------------------------------
// Layer-0 bidirectional LSTM (byte-identical to R13 best / 392us).
// ---------------------------------------------------------------------------
__global__ void __launch_bounds__(128, 1) lstm_layer0(
    const float* __restrict__ x,
    const float* __restrict__ wih_f, const float* __restrict__ whh_f,
    const float* __restrict__ bih_f, const float* __restrict__ bhh_f,
    const float* __restrict__ wih_b, const float* __restrict__ whh_b,
    const float* __restrict__ bih_b, const float* __restrict__ bhh_b)
{
    const int dir  = blockIdx.y;
    const int warp = threadIdx.x >> 5;
    const int j    = threadIdx.x & 31;
    const int b    = blockIdx.x * 4 + warp;

    const float* wih = dir ? wih_b : wih_f;
    const float* whh = dir ? whh_b : whh_f;
    const float* bih = dir ? bih_b : bih_f;
    const float* bhh = dir ? bhh_b : bhh_f;

    const float sc[4] = {SCONST, SCONST, KCONST, SCONST};

    unsigned long long wk[4][16];
#pragma unroll
    for (int q = 0; q < 4; q++) {
        const float4* r = reinterpret_cast<const float4*>(whh + (q * 32 + j) * 32);
        const float s = sc[q];
#pragma unroll
        for (int v = 0; v < 8; v++) {
            float4 f = r[v];
            wk[q][2*v]   = pack2(f.x * s, f.y * s);
            wk[q][2*v+1] = pack2(f.z * s, f.w * s);
        }
    }
    float wi[4][3], bias[4];
#pragma unroll
    for (int q = 0; q < 4; q++) {
        const int row = q * 32 + j;
        const float s = sc[q];
        wi[q][0] = wih[row*3+0] * s;
        wi[q][1] = wih[row*3+1] * s;
        wi[q][2] = wih[row*3+2] * s;
        bias[q]  = (bih[row] + bhh[row]) * s;
    }

    __shared__ __align__(16) float hx[4][32];
    const unsigned st_addr = (unsigned)__cvta_generic_to_shared(&hx[warp][j]);
    const unsigned ld_base = (unsigned)__cvta_generic_to_shared(&hx[warp][0]);

    const float* xb = x + (size_t)b * Tn * 3;
    const int xstep = dir ? -3 : 3;
    const float* xpf = dir ? (xb + (Tn - 1) * 3) : xb;
    float pfx[2][3];
#pragma unroll
    for (int s = 0; s < 2; s++) {
        pfx[s][0] = __ldg(xpf + 0);
        pfx[s][1] = __ldg(xpf + 1);
        pfx[s][2] = __ldg(xpf + 2);
        xpf += xstep;
    }

    float* obp = g_h0 + (size_t)b * Tn * 64 + dir * 32 + j
               + (dir ? (size_t)(Tn - 1) * 64 : 0);
    const int ostep = dir ? -64 : 64;

    float h = 0.0f, C = 0.0f;   // C = K * c
    for (int t = 0; t < Tn; t++) {
        const int s = t & 1;

        float zx[4];
#pragma unroll
        for (int q = 0; q < 4; q++)
            zx[q] = fmaf(wi[q][2], pfx[s][2],
                    fmaf(wi[q][1], pfx[s][1],
                    fmaf(wi[q][0], pfx[s][0], bias[q])));

        if (t + 2 < Tn) {
            pfx[s][0] = __ldg(xpf + 0);
            pfx[s][1] = __ldg(xpf + 1);
            pfx[s][2] = __ldg(xpf + 2);
            xpf += xstep;
        }

        sts_f32(st_addr, h);
        unsigned long long hp[16];
#pragma unroll
        for (int v = 0; v < 8; v++) lds_v2u64(ld_base + 16u * v, hp[2*v], hp[2*v+1]);

        // phase 1: gates i,f,g
        unsigned long long a0[3], a1[3];
#pragma unroll
        for (int q = 0; q < 3; q++) { a0[q] = pack2(zx[q], 0.0f); a1[q] = 0ull; }
#pragma unroll
        for (int v = 0; v < 8; v++) {
#pragma unroll
            for (int q = 0; q < 3; q++) {
                ffma2(a0[q], wk[q][2*v],   hp[2*v]);
                ffma2(a1[q], wk[q][2*v+1], hp[2*v+1]);
            }
        }
        const float z0 = combine_z(a0[0], a1[0]);
        const float z1 = combine_z(a0[1], a1[1]);
        const float z2 = combine_z(a0[2], a1[2]);

        const float ig  = sig_pre(z0);
        const float fg  = sig_pre(z1);
        const float ggK = fmaf(-2.0f * KCONST, rcpf(1.0f + ex2f(z2)), KCONST);
        C = fmaf(fg, C, ig * ggK);
        const float eC = ex2f(C);

        // phase 2: o-gate
        unsigned long long b0 = pack2(zx[3], 0.0f), b1 = 0ull;
#pragma unroll
        for (int v = 0; v < 8; v++) {
            ffma2(b0, wk[3][2*v],   hp[2*v]);
            ffma2(b1, wk[3][2*v+1], hp[2*v+1]);
        }
        const float z3 = combine_z(b0, b1);
        const float og = sig_pre(z3);

        const float th = fmaf(-2.0f, rcpf(1.0f + eC), 1.0f);
        h = og * th;

        *obp = h;
        obp += ostep;
    }
}

// ---------------------------------------------------------------------------
// Layer-1 input projection GEMM (byte-identical to R13 best: 128 threads,
// 8 timesteps per block — this config is at the FFMA2 floor).
// ---------------------------------------------------------------------------
__global__ void __launch_bounds__(128) gx1_gemm(
    const float* __restrict__ wih1_f, const float* __restrict__ bih1_f, const float* __restrict__ bhh1_f,
    const float* __restrict__ wih1_b, const float* __restrict__ bih1_b, const float* __restrict__ bhh1_b)
{
    const int t0  = blockIdx.x * 8;
    const int b0  = blockIdx.y * 32;
    const int dir = blockIdx.z;
    const float* w  = dir ? wih1_b : wih1_f;
    const float* bi = dir ? bih1_b : bih1_f;
    const float* bh = dir ? bhh1_b : bhh1_f;

    __shared__ __align__(16) float w_s[64 * 132];
    __shared__ __align__(16) float h_s[64 * 36];
    __shared__ float bias_s[128];

    const int tid = threadIdx.x;
    for (int i = tid; i < 128 * 64; i += 128) {
        const int k = i & 63, g = i >> 6;
        const float s = ((g >> 5) == 2) ? KCONST : SCONST;
        w_s[k * 132 + g] = w[g * 64 + k] * s;
    }
    {
        const float s = ((tid >> 5) == 2) ? KCONST : SCONST;
        bias_s[tid] = (bi[tid] + bh[tid]) * s;
    }

    const int gl = (tid & 31) * 4;
    const int bq = tid >> 5;
    const unsigned h_base = (unsigned)__cvta_generic_to_shared(&h_s[0]) + bq * 32u;

    for (int it = 0; it < 8; it++) {
        const int t = t0 + it;
        __syncthreads();
        for (int i = tid; i < 32 * 64; i += 128) {
            const int k = i & 63, bb = i >> 6;
            h_s[k * 36 + bb] = g_h0[((size_t)(b0 + bb) * Tn + t) * 64 + k];
        }
        __syncthreads();

        unsigned long long acc[4][4];
#pragma unroll
        for (int g = 0; g < 4; g++) {
            unsigned long long bg = dup2(bias_s[gl + g]);
#pragma unroll
            for (int p = 0; p < 4; p++) acc[g][p] = bg;
        }

#pragma unroll 4
        for (int k = 0; k < 64; k++) {
            const float4 wv = *reinterpret_cast<const float4*>(&w_s[k * 132 + gl]);
            unsigned long long wd[4];
            wd[0] = dup2(wv.x); wd[1] = dup2(wv.y); wd[2] = dup2(wv.z); wd[3] = dup2(wv.w);
            unsigned long long hp[4];
            lds_v2u64(h_base + (unsigned)(k * 144),      hp[0], hp[1]);
            lds_v2u64(h_base + (unsigned)(k * 144) + 16, hp[2], hp[3]);
#pragma unroll
            for (int g = 0; g < 4; g++)
#pragma unroll
                for (int p = 0; p < 4; p++) ffma2(acc[g][p], wd[g], hp[p]);
        }

        float* outb = g_gx1 + (((size_t)dir * Tn + t) * Bn + b0 + bq * 8) * 128 + gl;
#pragma unroll
        for (int p = 0; p < 4; p++) {
            float v0e, v0o, v1e, v1o, v2e, v2o, v3e, v3o;
            unpack2(acc[0][p], v0e, v0o);
            unpack2(acc[1][p], v1e, v1o);
            unpack2(acc[2][p], v2e, v2o);
            unpack2(acc[3][p], v3e, v3o);
            float4 lo = make_float4(v0e, v1e, v2e, v3e);
            float4 hi = make_float4(v0o, v1o, v2o, v3o);
            *reinterpret_cast<float4*>(outb + (size_t)(2 * p) * 128)     = lo;
            *reinterpret_cast<float4*>(outb + (size_t)(2 * p + 1) * 128) = hi;
        }
    }
}

// ---------------------------------------------------------------------------
// Layer-1 bidirectional LSTM (R13 hot loop) + pair-fused classifier tail.
// The pair {(bx, fwd), (bx, bwd)} produces rows 4bx..4bx+3 of hn; the SECOND
// block of each pair to finish classifies those 4 rows (1 row per warp —
// same chip-wide parallelism as the standalone kernel, zero launch cost).
// ---------------------------------------------------------------------------
__global__ void __launch_bounds__(128, 1) lstm_layer1(
    const float* __restrict__ whh_f, const float* __restrict__ whh_b,
    const float* __restrict__ wc1, const float* __restrict__ bc1,
    const float* __restrict__ wc2, const float* __restrict__ bc2,
    float* __restrict__ out)
{
    const int dir  = blockIdx.y;
    const int warp = threadIdx.x >> 5;
    const int j    = threadIdx.x & 31;
    const int b    = blockIdx.x * 4 + warp;
    const float* whh = dir ? whh_b : whh_f;

    const float sc[4] = {SCONST, SCONST, KCONST, SCONST};
    unsigned long long wk[4][16];
#pragma unroll
    for (int q = 0; q < 4; q++) {
        const float4* r = reinterpret_cast<const float4*>(whh + (q * 32 + j) * 32);
        const float s = sc[q];
#pragma unroll
        for (int v = 0; v < 8; v++) {
            float4 f = r[v];
            wk[q][2*v]   = pack2(f.x * s, f.y * s);
            wk[q][2*v+1] = pack2(f.z * s, f.w * s);
        }
    }

    __shared__ __align__(16) float hx[4][32];
    const unsigned st_addr = (unsigned)__cvta_generic_to_shared(&hx[warp][j]);
    const unsigned ld_base = (unsigned)__cvta_generic_to_shared(&hx[warp][0]);

    const long long gstep = dir ? -(long long)Bn * 128 : (long long)Bn * 128;
    const float* gpf = g_gx1 + (size_t)dir * Tn * Bn * 128 + (size_t)b * 128 + j
                     + (dir ? (size_t)(Tn - 1) * Bn * 128 : 0);

    float pf[4][4];
#pragma unroll
    for (int s = 0; s < 4; s++) {
#pragma unroll
        for (int q = 0; q < 4; q++) pf[s][q] = __ldg(gpf + q * 32);
        gpf += gstep;
    }

    float h = 0.0f, C = 0.0f;
    for (int t = 0; t < Tn; t++) {
        const int s = t & 3;
        float zx[4];
#pragma unroll
        for (int q = 0; q < 4; q++) zx[q] = pf[s][q];

        if (t + 4 < Tn) {
#pragma unroll
            for (int q = 0; q < 4; q++) pf[s][q] = __ldg(gpf + q * 32);
            gpf += gstep;
        }

        sts_f32(st_addr, h);
        unsigned long long hp[16];
#pragma unroll
        for (int v = 0; v < 8; v++) lds_v2u64(ld_base + 16u * v, hp[2*v], hp[2*v+1]);

        // phase 1: i,f,g
        unsigned long long a0[3], a1[3];
#pragma unroll
        for (int q = 0; q < 3; q++) { a0[q] = pack2(zx[q], 0.0f); a1[q] = 0ull; }
#pragma unroll
        for (int v = 0; v < 8; v++) {
#pragma unroll
            for (int q = 0; q < 3; q++) {
                ffma2(a0[q], wk[q][2*v],   hp[2*v]);
                ffma2(a1[q], wk[q][2*v+1], hp[2*v+1]);
            }
        }
        const float z0 = combine_z(a0[0], a1[0]);
        const float z1 = combine_z(a0[1], a1[1]);
        const float z2 = combine_z(a0[2], a1[2]);

        const float ig  = sig_pre(z0);
        const float fg  = sig_pre(z1);
        const float ggK = fmaf(-2.0f * KCONST, rcpf(1.0f + ex2f(z2)), KCONST);
        C = fmaf(fg, C, ig * ggK);
        const float eC = ex2f(C);

        // phase 2: o-gate
        unsigned long long b0 = pack2(zx[3], 0.0f), b1 = 0ull;
#pragma unroll
        for (int v = 0; v < 8; v++) {
            ffma2(b0, wk[3][2*v],   hp[2*v]);
            ffma2(b1, wk[3][2*v+1], hp[2*v+1]);
        }
        const float z3 = combine_z(b0, b1);
        const float og = sig_pre(z3);

        const float th = fmaf(-2.0f, rcpf(1.0f + eC), 1.0f);
        h = og * th;
    }

    g_hn[b * 64 + dir * 32 + j] = h;

    // ---- pair-fused classifier tail ----
    __shared__ unsigned is_last;
    __threadfence();                       // publish this block's g_hn quarter
    __syncthreads();                       // all 4 warps' stores fenced
    if (threadIdx.x == 0) {
        unsigned old = atomicAdd(&g_pair_done[blockIdx.x], 1u);
        is_last = (old == 1u) ? 1u : 0u;   // second block of the pair wins
    }
    __syncthreads();
    if (is_last) {
        if (threadIdx.x == 0) g_pair_done[blockIdx.x] = 0;  // reset for replay
        // warp w classifies row 4*bx + w (its hn: our half in L1, peer via L2)
        const int row = blockIdx.x * 4 + warp;
        const float4* wr = reinterpret_cast<const float4*>(wc1 + j * 64);
        const float4* hr = reinterpret_cast<const float4*>(g_hn + row * 64);
        float a = __ldg(bc1 + j);
#pragma unroll
        for (int v = 0; v < 16; v++) {
            float4 w4 = __ldg(wr + v);
            float4 h4 = hr[v];
            a += w4.x * h4.x + w4.y * h4.y + w4.z * h4.z + w4.w * h4.w;
        }
        a = fmaxf(a, 0.0f);
        float p0 = a * __ldg(wc2 + j);
        float p1 = a * __ldg(wc2 + 32 + j);
#pragma unroll
        for (int off = 16; off > 0; off >>= 1) {
            p0 += __shfl_xor_sync(0xffffffffu, p0, off);
            p1 += __shfl_xor_sync(0xffffffffu, p1, off);
        }
        if (j == 0) {
            out[row * 2 + 0] = p0 + __ldg(bc2 + 0);
            out[row * 2 + 1] = p1 + __ldg(bc2 + 1);
        }
    }
}

// ---------------------------------------------------------------------------
extern "C" void kernel_launch(void* const* d_in, const int* in_sizes, int n_in,
                              void* d_out, int out_size)
{
    (void)in_sizes; (void)n_in; (void)out_size;
    const float* x     = (const float*)d_in[0];
    const float* wih0f = (const float*)d_in[1];
    const float* whh0f = (const float*)d_in[2];
    const float* bih0f = (const float*)d_in[3];
    const float* bhh0f = (const float*)d_in[4];
    const float* wih0b = (const float*)d_in[5];
    const float* whh0b = (const float*)d_in[6];
    const float* bih0b = (const float*)d_in[7];
    const float* bhh0b = (const float*)d_in[8];
    const float* wih1f = (const float*)d_in[9];
    const float* whh1f = (const float*)d_in[10];
    const float* bih1f = (const float*)d_in[11];
    const float* bhh1f = (const float*)d_in[12];
    const float* wih1b = (const float*)d_in[13];
    const float* whh1b = (const float*)d_in[14];
    const float* bih1b = (const float*)d_in[15];
    const float* bhh1b = (const float*)d_in[16];
    const float* wc1   = (const float*)d_in[17];
    const float* bc1   = (const float*)d_in[18];
    const float* wc2   = (const float*)d_in[19];
    const float* bc2   = (const float*)d_in[20];

    lstm_layer0<<<dim3(Bn / 4, 2), 128>>>(x, wih0f, whh0f, bih0f, bhh0f,
                                          wih0b, whh0b, bih0b, bhh0b);
    gx1_gemm<<<dim3(Tn / 8, Bn / 32, 2), 128>>>(wih1f, bih1f, bhh1f,
                                                wih1b, bih1b, bhh1b);
    lstm_layer1<<<dim3(Bn / 4, 2), 128>>>(whh1f, whh1b,
                                          wc1, bc1, wc2, bc2, (float*)d_out);
}